// round 5
// baseline (speedup 1.0000x reference)
#include <cuda_runtime.h>
#include <math.h>

#define NB 16
#define HW 3136
#define CC 256
#define OH 224
#define OW 224
#define RR 16
#define KS 33
#define NOUT (NB*OH*OW)

__device__ float g_mask56[NB * HW];
__device__ float g_tmp[NOUT];

// ---------------------------------------------------------------------------
// Kernel 1: per-pixel Mahalanobis distance via symmetric (upper-triangle)
// evaluation with PERFECT warp balance.
// Triangle {(i,c): i<=c} decomposed into 72 tiles of 16 rows x 32 cols:
// tile (R,C) present iff R <= 2C+1. Warp w owns tiles {w, w+8, ..., w+64}
// -> exactly 9 tiles = 144 rows per warp, so all warps retire together and
// the SM never starves late in the CTA.
// Per tile: acct[b] (f32x2 pairs) accumulates sum_i M[i][col]*d_i[b]; the
// epilogue folds acct * d_col into accg. Diagonal tiles (R in {2C,2C+1})
// are lane-predicated (row <= col), capture Mcc, and fold the
// -0.5*Mcc*d_c^2 correction, so quad = 2 * total(accg).
// ---------------------------------------------------------------------------
__global__ __launch_bounds__(256) void maha_kernel(
    const float* __restrict__ x, const float* __restrict__ mean,
    const float* __restrict__ M) {
  const int p = blockIdx.x;
  const int t = threadIdx.x;
  const int wid = t >> 5, lane = t & 31;
  __shared__ float sd[CC][NB];   // transposed diff: sd[channel][batch]
  __shared__ float red[8][NB];

  {
    const float mu = mean[p * CC + t];
    const float* xp = x + (size_t)p * CC + t;
#pragma unroll
    for (int b = 0; b < NB; b++)
      sd[t][b] = xp[(size_t)b * ((size_t)HW * CC)] - mu;
  }
  __syncthreads();

  const float* Mp = M + ((size_t)p << 16);
  const unsigned sbase = (unsigned)__cvta_generic_to_shared(&sd[0][0]);

  unsigned long long accg[8];
#pragma unroll
  for (int j = 0; j < 8; j++) accg[j] = 0ull;

#pragma unroll 1
  for (int k = wid; k < 72; k += 8) {
    // map flat tile index k -> (C, R): offset[C] = C*(C+1)
    int C = 0;
#pragma unroll
    for (int cc = 1; cc < 8; cc++)
      if (k >= cc * (cc + 1)) C = cc;
    const int R = k - C * (C + 1);
    const int r0 = R << 4;
    const int col = (C << 5) + lane;
    const float* Mc = Mp + col;
    const bool isdiag = (R >= 2 * C);

    unsigned long long acct[8];
#pragma unroll
    for (int j = 0; j < 8; j++) acct[j] = 0ull;
    float Mcc = 0.0f;

    if (!isdiag) {
#pragma unroll
      for (int h = 0; h < 16; h += 8) {
        float m[8];
#pragma unroll
        for (int u = 0; u < 8; u++) m[u] = Mc[(size_t)(r0 + h + u) * CC];
#pragma unroll
        for (int u = 0; u < 8; u++) {
          unsigned long long m2;
          asm("mov.b64 %0, {%1, %1};" : "=l"(m2) : "f"(m[u]));
          const unsigned ra = sbase + (r0 + h + u) * 64;
          unsigned long long d0, d1, d2, d3, d4, d5, d6, d7;
          asm("ld.shared.v2.u64 {%0,%1}, [%2];" : "=l"(d0), "=l"(d1) : "r"(ra));
          asm("ld.shared.v2.u64 {%0,%1}, [%2];" : "=l"(d2), "=l"(d3) : "r"(ra + 16));
          asm("ld.shared.v2.u64 {%0,%1}, [%2];" : "=l"(d4), "=l"(d5) : "r"(ra + 32));
          asm("ld.shared.v2.u64 {%0,%1}, [%2];" : "=l"(d6), "=l"(d7) : "r"(ra + 48));
          asm("fma.rn.f32x2 %0, %1, %2, %0;" : "+l"(acct[0]) : "l"(m2), "l"(d0));
          asm("fma.rn.f32x2 %0, %1, %2, %0;" : "+l"(acct[1]) : "l"(m2), "l"(d1));
          asm("fma.rn.f32x2 %0, %1, %2, %0;" : "+l"(acct[2]) : "l"(m2), "l"(d2));
          asm("fma.rn.f32x2 %0, %1, %2, %0;" : "+l"(acct[3]) : "l"(m2), "l"(d3));
          asm("fma.rn.f32x2 %0, %1, %2, %0;" : "+l"(acct[4]) : "l"(m2), "l"(d4));
          asm("fma.rn.f32x2 %0, %1, %2, %0;" : "+l"(acct[5]) : "l"(m2), "l"(d5));
          asm("fma.rn.f32x2 %0, %1, %2, %0;" : "+l"(acct[6]) : "l"(m2), "l"(d6));
          asm("fma.rn.f32x2 %0, %1, %2, %0;" : "+l"(acct[7]) : "l"(m2), "l"(d7));
        }
      }
    } else {
#pragma unroll
      for (int h = 0; h < 16; h += 8) {
        float m[8];
#pragma unroll
        for (int u = 0; u < 8; u++) m[u] = Mc[(size_t)(r0 + h + u) * CC];
#pragma unroll
        for (int u = 0; u < 8; u++) {
          const int rr = r0 + h + u - (C << 5);  // row - colblock base
          const float mv = (rr <= lane) ? m[u] : 0.0f;
          if (rr == lane) Mcc = m[u];
          unsigned long long m2;
          asm("mov.b64 %0, {%1, %1};" : "=l"(m2) : "f"(mv));
          const unsigned ra = sbase + (r0 + h + u) * 64;
          unsigned long long d0, d1, d2, d3, d4, d5, d6, d7;
          asm("ld.shared.v2.u64 {%0,%1}, [%2];" : "=l"(d0), "=l"(d1) : "r"(ra));
          asm("ld.shared.v2.u64 {%0,%1}, [%2];" : "=l"(d2), "=l"(d3) : "r"(ra + 16));
          asm("ld.shared.v2.u64 {%0,%1}, [%2];" : "=l"(d4), "=l"(d5) : "r"(ra + 32));
          asm("ld.shared.v2.u64 {%0,%1}, [%2];" : "=l"(d6), "=l"(d7) : "r"(ra + 48));
          asm("fma.rn.f32x2 %0, %1, %2, %0;" : "+l"(acct[0]) : "l"(m2), "l"(d0));
          asm("fma.rn.f32x2 %0, %1, %2, %0;" : "+l"(acct[1]) : "l"(m2), "l"(d1));
          asm("fma.rn.f32x2 %0, %1, %2, %0;" : "+l"(acct[2]) : "l"(m2), "l"(d2));
          asm("fma.rn.f32x2 %0, %1, %2, %0;" : "+l"(acct[3]) : "l"(m2), "l"(d3));
          asm("fma.rn.f32x2 %0, %1, %2, %0;" : "+l"(acct[4]) : "l"(m2), "l"(d4));
          asm("fma.rn.f32x2 %0, %1, %2, %0;" : "+l"(acct[5]) : "l"(m2), "l"(d5));
          asm("fma.rn.f32x2 %0, %1, %2, %0;" : "+l"(acct[6]) : "l"(m2), "l"(d6));
          asm("fma.rn.f32x2 %0, %1, %2, %0;" : "+l"(acct[7]) : "l"(m2), "l"(d7));
        }
      }
    }

    // epilogue: accg += acct * d_col  (diag: accg += (acct - 0.5*Mcc*d)*d)
    const unsigned dca = sbase + col * 64;
    unsigned long long dc[8];
    asm("ld.shared.v2.u64 {%0,%1}, [%2];" : "=l"(dc[0]), "=l"(dc[1]) : "r"(dca));
    asm("ld.shared.v2.u64 {%0,%1}, [%2];" : "=l"(dc[2]), "=l"(dc[3]) : "r"(dca + 16));
    asm("ld.shared.v2.u64 {%0,%1}, [%2];" : "=l"(dc[4]), "=l"(dc[5]) : "r"(dca + 32));
    asm("ld.shared.v2.u64 {%0,%1}, [%2];" : "=l"(dc[6]), "=l"(dc[7]) : "r"(dca + 48));
    if (!isdiag) {
#pragma unroll
      for (int j = 0; j < 8; j++)
        asm("fma.rn.f32x2 %0, %1, %2, %0;" : "+l"(accg[j]) : "l"(acct[j]), "l"(dc[j]));
    } else {
      const float nh = -0.5f * Mcc;
      unsigned long long nh2;
      asm("mov.b64 %0, {%1, %1};" : "=l"(nh2) : "f"(nh));
#pragma unroll
      for (int j = 0; j < 8; j++) {
        unsigned long long tmp = acct[j];
        asm("fma.rn.f32x2 %0, %1, %2, %0;" : "+l"(tmp) : "l"(nh2), "l"(dc[j]));
        asm("fma.rn.f32x2 %0, %1, %2, %0;" : "+l"(accg[j]) : "l"(tmp), "l"(dc[j]));
      }
    }
  }

  float q[NB];
#pragma unroll
  for (int j = 0; j < 8; j++) {
    float lo, hi;
    asm("mov.b64 {%0, %1}, %2;" : "=f"(lo), "=f"(hi) : "l"(accg[j]));
    q[2 * j] = lo;
    q[2 * j + 1] = hi;
  }
#pragma unroll
  for (int b = 0; b < NB; b++) {
#pragma unroll
    for (int off = 16; off > 0; off >>= 1)
      q[b] += __shfl_down_sync(0xffffffffu, q[b], off);
  }
  if (lane == 0) {
#pragma unroll
    for (int b = 0; b < NB; b++) red[wid][b] = q[b];
  }
  __syncthreads();
  if (t < NB) {
    float s = 0.f;
#pragma unroll
    for (int w = 0; w < 8; w++) s += red[w][t];
    g_mask56[t * HW + p] = sqrtf(fmaxf(2.0f * s, 0.f));
  }
}

__device__ __forceinline__ int reflect101(int i) {
  if (i < 0) i = -i;
  if (i > 223) i = 446 - i;
  return i;
}

__device__ __forceinline__ void load_weights(float* w, float* inv) {
  const int tid = threadIdx.x;
  if (tid < KS) {
    const float d = (float)(tid - RR);
    w[tid] = expf(-(d * d) / 32.0f);
  }
  __syncthreads();
  if (tid == 0) {
    float s = 0.f;
    for (int j = 0; j < KS; j++) s += w[j];
    *inv = 1.0f / s;
  }
}

// ---------------------------------------------------------------------------
// Kernel 2: FUSED bilinear resize (56->224) + vertical blur. Also zeroes the
// score outputs (block 0) so blur_h's atomicMax starts clean. grid = 224.
// ---------------------------------------------------------------------------
__global__ __launch_bounds__(256) void blur_v_kernel(float* __restrict__ score) {
  __shared__ float s[OH + 32][17];
  __shared__ float w[KS];
  __shared__ float inv;
  load_weights(w, &inv);
  const int tid = threadIdx.x;
  if (blockIdx.x == 0 && tid < NB) score[tid] = 0.0f;
  const int b = blockIdx.x / 14;
  const int xt = (blockIdx.x % 14) * 16;
  const float* mp = g_mask56 + b * HW;
#pragma unroll
  for (int li = tid; li < (OH + 32) * 16; li += 256) {
    const int r = li >> 4, c = li & 15;
    const int gy = reflect101(r - RR);
    const int gx = xt + c;
    const float fy = (gy + 0.5f) * 0.25f - 0.5f;
    const float fx = (gx + 0.5f) * 0.25f - 0.5f;
    const int y0 = (int)floorf(fy);
    const int x0 = (int)floorf(fx);
    const float wy = fy - (float)y0;
    const float wx = fx - (float)x0;
    const int y0c = min(max(y0, 0), 55), y1c = min(max(y0 + 1, 0), 55);
    const int x0c = min(max(x0, 0), 55), x1c = min(max(x0 + 1, 0), 55);
    const float v00 = mp[y0c * 56 + x0c];
    const float v01 = mp[y0c * 56 + x1c];
    const float v10 = mp[y1c * 56 + x0c];
    const float v11 = mp[y1c * 56 + x1c];
    s[r][c] = (1.f - wy) * ((1.f - wx) * v00 + wx * v01) +
              wy * ((1.f - wx) * v10 + wx * v11);
  }
  __syncthreads();
  float* dst = g_tmp + b * OH * OW + xt;
  const int c = tid & 15;
  for (int y = tid >> 4; y < OH; y += 16) {
    float sum = 0.f;
#pragma unroll
    for (int j = 0; j < KS; j++) sum += w[j] * s[y + j][c];
    dst[y * OW + c] = sum * inv;
  }
}

// ---------------------------------------------------------------------------
// Kernel 3: horizontal blur + per-batch max. grid = 448.
// ---------------------------------------------------------------------------
__global__ __launch_bounds__(256) void blur_h_kernel(float* __restrict__ out_mask,
                                                     float* __restrict__ score) {
  __shared__ float s[8][256];
  __shared__ float w[KS];
  __shared__ float inv;
  __shared__ float smx[8];
  load_weights(w, &inv);
  const int tid = threadIdx.x;
  const int b = blockIdx.x / 28;
  const int yt = (blockIdx.x % 28) * 8;
  const float* src = g_tmp + (b * OH + yt) * OW;
#pragma unroll
  for (int li = tid; li < 8 * 256; li += 256) {
    const int r = li >> 8, c = li & 255;
    const int gx = reflect101(c - RR);
    s[r][c] = src[r * OW + gx];
  }
  __syncthreads();
  float* dst = out_mask + (b * OH + yt) * OW;
  const int lane = tid & 31;
  const int r = tid >> 5;
  float mx = 0.f;
#pragma unroll
  for (int x0 = 0; x0 < OW; x0 += 32) {
    const int x = x0 + lane;
    float sum = 0.f;
#pragma unroll
    for (int j = 0; j < KS; j++) sum += w[j] * s[r][x + j];
    sum *= inv;
    dst[r * OW + x] = sum;
    mx = fmaxf(mx, sum);
  }
#pragma unroll
  for (int off = 16; off > 0; off >>= 1)
    mx = fmaxf(mx, __shfl_down_sync(0xffffffffu, mx, off));
  if (lane == 0) smx[r] = mx;
  __syncthreads();
  if (tid == 0) {
    float m2 = smx[0];
#pragma unroll
    for (int k = 1; k < 8; k++) m2 = fmaxf(m2, smx[k]);
    atomicMax((int*)&score[b], __float_as_int(m2));
  }
}

extern "C" void kernel_launch(void* const* d_in, const int* in_sizes, int n_in,
                              void* d_out, int out_size) {
  const float* inputs = (const float*)d_in[0];    // [16,56,56,256]
  const float* mean = (const float*)d_in[1];      // [3136,256]
  const float* cvar_inv = (const float*)d_in[2];  // [3136,256,256]
  float* out = (float*)d_out;
  float* score = out;          // [16,1]
  float* mask = out + NB;      // [16,224,224,1]

  maha_kernel<<<HW, 256>>>(inputs, mean, cvar_inv);
  blur_v_kernel<<<16 * 14, 256>>>(score);
  blur_h_kernel<<<16 * 28, 256>>>(mask, score);
}